// round 5
// baseline (speedup 1.0000x reference)
#include <cuda_runtime.h>
#include <cstdint>

// FCGAT reduces exactly to  out = relu(x @ W_w^T + W_b):
//   a = softmax(e, axis=2)  =>  sum_j a[n,k,j] == 1
//   einsum('nkj,nkd->nkd', a, h) = h * sum_j a[n,k,j] = h
// so the attention branch (att_w, att_b, leaky_relu, softmax) is an identity.

#define M_TOT 32768   // N*K = 64*512 rows
#define E_TOT 256     // output features
#define K_TOT 256     // input features (d)
#define BM 128
#define BE 128
#define BK 32

#define X_ELEMS  8388608   // 64*512*256  (2^23)
#define WW_ELEMS 65536     // 256*256
#define WB_ELEMS 256

__global__ __launch_bounds__(256, 2)
void fcgat_gemm_bias_relu(const float* __restrict__ X,
                          const float* __restrict__ W,     // [E_TOT, K_TOT] row-major
                          const float* __restrict__ bias,  // [E_TOT]
                          float* __restrict__ out)
{
    __shared__ __align__(16) float As[BK][BM];  // As[d][m]  (A transposed)
    __shared__ __align__(16) float Bs[BK][BE];  // Bs[d][e]  (W transposed)

    const int tid = threadIdx.x;
    const int tx  = tid & 15;   // e direction (8 cols each)
    const int ty  = tid >> 4;   // m direction (8 rows each)
    const int e0  = blockIdx.x * BE;
    const int m0  = blockIdx.y * BM;

    // 8 rows x 4 packed f32x2 pairs (= 8 cols) of accumulators
    unsigned long long acc[8][4];
#pragma unroll
    for (int i = 0; i < 8; i++)
#pragma unroll
        for (int j = 0; j < 4; j++) acc[i][j] = 0ull;

    for (int k0 = 0; k0 < K_TOT; k0 += BK) {
        // ---- load tiles (each thread: 4 float4 from X, 4 float4 from W) ----
#pragma unroll
        for (int it = 0; it < 4; it++) {
            int loadId = tid + it * 256;        // 0..1023
            int row = loadId >> 3;              // 0..127
            int c4  = (loadId & 7) * 4;         // 0,4,...,28

            float4 va = *reinterpret_cast<const float4*>(
                &X[(size_t)(m0 + row) * K_TOT + k0 + c4]);
            As[c4 + 0][row] = va.x;
            As[c4 + 1][row] = va.y;
            As[c4 + 2][row] = va.z;
            As[c4 + 3][row] = va.w;

            float4 vb = *reinterpret_cast<const float4*>(
                &W[(size_t)(e0 + row) * K_TOT + k0 + c4]);
            Bs[c4 + 0][row] = vb.x;
            Bs[c4 + 1][row] = vb.y;
            Bs[c4 + 2][row] = vb.z;
            Bs[c4 + 3][row] = vb.w;
        }
        __syncthreads();

        // ---- inner product over the BK slice ----
#pragma unroll
        for (int dd = 0; dd < BK; dd++) {
            float4 a0 = *reinterpret_cast<const float4*>(&As[dd][ty * 8]);
            float4 a1 = *reinterpret_cast<const float4*>(&As[dd][ty * 8 + 4]);

            unsigned long long b[4];
            const unsigned long long* bp =
                reinterpret_cast<const unsigned long long*>(&Bs[dd][tx * 8]);
            b[0] = bp[0]; b[1] = bp[1]; b[2] = bp[2]; b[3] = bp[3];

            float am[8] = {a0.x, a0.y, a0.z, a0.w, a1.x, a1.y, a1.z, a1.w};
#pragma unroll
            for (int i = 0; i < 8; i++) {
                unsigned long long a2;
                asm("mov.b64 %0, {%1, %1};" : "=l"(a2) : "f"(am[i]));
#pragma unroll
                for (int j = 0; j < 4; j++)
                    asm("fma.rn.f32x2 %0, %1, %2, %0;"
                        : "+l"(acc[i][j]) : "l"(a2), "l"(b[j]));
            }
        }
        __syncthreads();
    }

    // ---- epilogue: bias + relu + store ----
    float bvals[8];
#pragma unroll
    for (int j = 0; j < 8; j++) bvals[j] = bias[e0 + tx * 8 + j];

#pragma unroll
    for (int i = 0; i < 8; i++) {
        float c[8];
#pragma unroll
        for (int j = 0; j < 4; j++) {
            float lo, hi;
            asm("mov.b64 {%0, %1}, %2;" : "=f"(lo), "=f"(hi) : "l"(acc[i][j]));
            c[2 * j]     = lo;
            c[2 * j + 1] = hi;
        }
#pragma unroll
        for (int j = 0; j < 8; j++) {
            c[j] += bvals[j];
            c[j] = fmaxf(c[j], 0.0f);
        }
        float4* dst = reinterpret_cast<float4*>(
            &out[(size_t)(m0 + ty * 8 + i) * E_TOT + e0 + tx * 8]);
        dst[0] = make_float4(c[0], c[1], c[2], c[3]);
        dst[1] = make_float4(c[4], c[5], c[6], c[7]);
    }
}

extern "C" void kernel_launch(void* const* d_in, const int* in_sizes, int n_in,
                              void* d_out, int out_size)
{
    // Positional defaults per metadata order: x, W_w, W_b, att_w, att_b.
    // (att_w / att_b are mathematically unused — softmax identity.)
    const float* x  = (n_in > 0) ? (const float*)d_in[0] : nullptr;
    const float* Ww = (n_in > 1) ? (const float*)d_in[1] : nullptr;
    const float* Wb = (n_in > 2) ? (const float*)d_in[2] : nullptr;

    // Override by exact element-count match (robust to reordering).
    for (int i = 0; i < n_in; i++) {
        if (in_sizes[i] == X_ELEMS)       x  = (const float*)d_in[i];
        else if (in_sizes[i] == WW_ELEMS) Ww = (const float*)d_in[i];
        else if (in_sizes[i] == WB_ELEMS) Wb = (const float*)d_in[i];
    }

    dim3 grid(E_TOT / BE, M_TOT / BM);   // (2, 256)
    fcgat_gemm_bias_relu<<<grid, 256>>>(x, Ww, Wb, (float*)d_out);
}

// round 12
// speedup vs baseline: 2.2852x; 2.2852x over previous
#include <cuda_runtime.h>
#include <cuda_bf16.h>
#include <cstdint>

// FCGAT reduces exactly to  out = relu(x @ W_w^T + W_b):
//   softmax over j sums to 1 against the 'nkj,nkd->nkd' einsum -> identity.
// GEMM M=32768 N=256 K=256 fp32, computed as 3-term bf16 split on HMMA
// (mma.sync m16n8k16 — base-target PTX; tcgen05 is rejected by this
//  harness's compute_103 PTX target).

#define M_TOT   32768
#define NDIM    256
#define KDIM    256
#define BM      128
#define BN      128
#define KC      32
#define NCHUNK  8

#define ROWB    80                 // 32 bf16 = 64B data + 16B pad (5 coprime 8)
#define ASZ     (128 * ROWB)       // 10240 B per matrix plane
#define STAGE   (4 * ASZ)          // A_hi, A_lo, B_hi, B_lo
#define SMEM_TOTAL (2 * STAGE)     // 81920 B (double buffered)

#define X_ELEMS  8388608
#define WW_ELEMS 65536
#define WB_ELEMS 256

// Pre-split W (bf16 hi + residual lo), written by a tiny pre-kernel.
__device__ __align__(16) unsigned short g_Whi[NDIM * KDIM];
__device__ __align__(16) unsigned short g_Wlo[NDIM * KDIM];

__global__ void wsplit_kernel(const float* __restrict__ W) {
    int i = blockIdx.x * 256 + threadIdx.x;   // grid 256 x 256 = 65536
    float f = W[i];
    __nv_bfloat16 hb = __float2bfloat16(f);
    float hf = __bfloat162float(hb);
    __nv_bfloat16 lb = __float2bfloat16(f - hf);
    g_Whi[i] = reinterpret_cast<unsigned short&>(hb);
    g_Wlo[i] = reinterpret_cast<unsigned short&>(lb);
}

// ---------------- PTX helpers (base-target only) ----------------
__device__ __forceinline__ uint32_t smem_u32(const void* p) {
    uint32_t a;
    asm("{ .reg .u64 t; cvta.to.shared.u64 t, %1; cvt.u32.u64 %0, t; }"
        : "=r"(a) : "l"(p));
    return a;
}
__device__ __forceinline__ void ldsm4(uint32_t* r, uint32_t addr) {
    asm volatile("ldmatrix.sync.aligned.m8n8.x4.shared.b16 {%0,%1,%2,%3}, [%4];"
                 : "=r"(r[0]), "=r"(r[1]), "=r"(r[2]), "=r"(r[3]) : "r"(addr));
}
__device__ __forceinline__ void mma_bf16(float* c, const uint32_t* a,
                                         const uint32_t* b) {
    asm("mma.sync.aligned.m16n8k16.row.col.f32.bf16.bf16.f32 "
        "{%0,%1,%2,%3},{%4,%5,%6,%7},{%8,%9},{%0,%1,%2,%3};"
        : "+f"(c[0]), "+f"(c[1]), "+f"(c[2]), "+f"(c[3])
        : "r"(a[0]), "r"(a[1]), "r"(a[2]), "r"(a[3]), "r"(b[0]), "r"(b[1]));
}
__device__ __forceinline__ void cpasync16(uint32_t dst, const void* src) {
    asm volatile("cp.async.cg.shared.global [%0], [%1], 16;"
                 :: "r"(dst), "l"(src) : "memory");
}
#define STS128(a, r0, r1, r2, r3) \
    asm volatile("st.shared.v4.b32 [%0], {%1,%2,%3,%4};" \
                 :: "r"(a), "r"(r0), "r"(r1), "r"(r2), "r"(r3) : "memory")

// Load 16 fp32, split to bf16 hi/lo, store (2+2) x 16B into padded smem rows.
__device__ __forceinline__ void load_x_chunk(const float* __restrict__ src,
                                             uint32_t dstHi) {
    const float4* p = reinterpret_cast<const float4*>(src);
    float4 f0 = p[0], f1 = p[1], f2 = p[2], f3 = p[3];
    float v[16] = {f0.x, f0.y, f0.z, f0.w, f1.x, f1.y, f1.z, f1.w,
                   f2.x, f2.y, f2.z, f2.w, f3.x, f3.y, f3.z, f3.w};
    uint32_t h[8], l[8];
#pragma unroll
    for (int j = 0; j < 8; j++) {
        float a = v[2 * j], b = v[2 * j + 1];
        uint32_t hp;
        asm("cvt.rn.bf16x2.f32 %0, %1, %2;" : "=r"(hp) : "f"(b), "f"(a));
        float ha = __uint_as_float(hp << 16);
        float hb = __uint_as_float(hp & 0xFFFF0000u);
        uint32_t lp;
        asm("cvt.rn.bf16x2.f32 %0, %1, %2;" : "=r"(lp) : "f"(b - hb), "f"(a - ha));
        h[j] = hp; l[j] = lp;
    }
    STS128(dstHi,            h[0], h[1], h[2], h[3]);
    STS128(dstHi + 16,       h[4], h[5], h[6], h[7]);
    STS128(dstHi + ASZ,      l[0], l[1], l[2], l[3]);
    STS128(dstHi + ASZ + 16, l[4], l[5], l[6], l[7]);
}

// cp.async W chunk (hi+lo), 4 x 16B per thread, register-free.
__device__ __forceinline__ void load_w_chunk(int c, uint32_t dstHiBase,
                                             int row, int half, int n0) {
    const unsigned short* sh = &g_Whi[(size_t)(n0 + row) * KDIM + c * KC + half * 16];
    const unsigned short* sl = &g_Wlo[(size_t)(n0 + row) * KDIM + c * KC + half * 16];
    uint32_t d = dstHiBase + row * ROWB + half * 32;
    cpasync16(d,            sh);
    cpasync16(d + 16,       sh + 8);
    cpasync16(d + ASZ,      sl);
    cpasync16(d + ASZ + 16, sl + 8);
}

// =========================== main kernel ===========================
__global__ __launch_bounds__(256, 2)
void fcgat_mma(const float* __restrict__ X,
               const float* __restrict__ bias,
               float* __restrict__ out)
{
    extern __shared__ __align__(1024) char smem[];
    const uint32_t sb = smem_u32(smem);
    const int tid  = threadIdx.x;
    const int lane = tid & 31;
    const int wid  = tid >> 5;
    const int warp_m = wid & 1;      // 2 warps over M (64 rows each)
    const int warp_n = wid >> 1;     // 4 warps over N (32 cols each)

    // producer mapping: 256 threads cover 128 rows x 2 column-halves
    const int row  = tid & 127;
    const int half = tid >> 7;
    const int n0 = blockIdx.x * BN;
    const float* Xt = X + (size_t)(blockIdx.y * BM + row) * KDIM + half * 16;
    const uint32_t aDst = sb + row * ROWB + half * 32;           // + bufOff
    const uint32_t bDst = sb + 2 * ASZ;                          // + bufOff

    // ldmatrix lane address precompute
    const int i4 = lane >> 3;
    const uint32_t aBase = sb + (warp_m * 64 + (i4 & 1) * 8 + (lane & 7)) * ROWB
                              + (i4 >> 1) * 16;
    const uint32_t bBase = sb + 2 * ASZ
                              + (warp_n * 32 + (i4 >> 1) * 8 + (lane & 7)) * ROWB
                              + (i4 & 1) * 16;

    float acc[4][4][4];
#pragma unroll
    for (int a = 0; a < 4; a++)
#pragma unroll
        for (int b = 0; b < 4; b++)
#pragma unroll
            for (int d = 0; d < 4; d++) acc[a][b][d] = 0.0f;

    // ---- prologue: chunk 0 into buffer 0 ----
    load_w_chunk(0, bDst, row, half, n0);
    asm volatile("cp.async.commit_group;" ::: "memory");
    load_x_chunk(Xt, aDst);
    asm volatile("cp.async.wait_group 0;" ::: "memory");
    __syncthreads();

    for (int c = 0; c < NCHUNK; c++) {
        const uint32_t bufOff  = (uint32_t)(c & 1) * STAGE;
        const uint32_t nBufOff = bufOff ^ STAGE;

        if (c < NCHUNK - 1) {
            load_w_chunk(c + 1, bDst + nBufOff, row, half, n0);
            asm volatile("cp.async.commit_group;" ::: "memory");
        }

        // ---- MMA over this K-chunk (2 k16 steps x 3 split terms) ----
#pragma unroll
        for (int ks = 0; ks < 2; ks++) {
            const uint32_t ao = aBase + bufOff + ks * 32;
            const uint32_t bo = bBase + bufOff + ks * 32;
            uint32_t ah[16], bh[8], bl[8];
            ldsm4(bh + 0, bo);
            ldsm4(bh + 4, bo + 1280);
            ldsm4(bl + 0, bo + ASZ);
            ldsm4(bl + 4, bo + ASZ + 1280);
#pragma unroll
            for (int tm = 0; tm < 4; tm++) ldsm4(ah + tm * 4, ao + tm * 1280);
#pragma unroll
            for (int tm = 0; tm < 4; tm++)
#pragma unroll
                for (int tn = 0; tn < 4; tn++)
                    mma_bf16(acc[tm][tn], ah + tm * 4, bh + tn * 2);  // hi*hi
#pragma unroll
            for (int tm = 0; tm < 4; tm++)
#pragma unroll
                for (int tn = 0; tn < 4; tn++)
                    mma_bf16(acc[tm][tn], ah + tm * 4, bl + tn * 2);  // hi*lo
#pragma unroll
            for (int tm = 0; tm < 4; tm++) ldsm4(ah + tm * 4, ao + ASZ + tm * 1280);
#pragma unroll
            for (int tm = 0; tm < 4; tm++)
#pragma unroll
                for (int tn = 0; tn < 4; tn++)
                    mma_bf16(acc[tm][tn], ah + tm * 4, bh + tn * 2);  // lo*hi
        }

        if (c < NCHUNK - 1)
            load_x_chunk(Xt + (c + 1) * KC, aDst + nBufOff);
        asm volatile("cp.async.wait_group 0;" ::: "memory");
        __syncthreads();
    }

    // ---- epilogue: bias + relu, straight from fragments ----
    const int m0 = blockIdx.y * BM + warp_m * 64 + (lane >> 2);
    const int colBase = n0 + warp_n * 32 + (lane & 3) * 2;
#pragma unroll
    for (int tn = 0; tn < 4; tn++) {
        const int col = colBase + tn * 8;
        const float2 bv = *reinterpret_cast<const float2*>(&bias[col]);
#pragma unroll
        for (int tm = 0; tm < 4; tm++) {
            const int r = m0 + tm * 16;
            float2 o0, o1;
            o0.x = fmaxf(acc[tm][tn][0] + bv.x, 0.0f);
            o0.y = fmaxf(acc[tm][tn][1] + bv.y, 0.0f);
            o1.x = fmaxf(acc[tm][tn][2] + bv.x, 0.0f);
            o1.y = fmaxf(acc[tm][tn][3] + bv.y, 0.0f);
            *reinterpret_cast<float2*>(&out[(size_t)r * NDIM + col])       = o0;
            *reinterpret_cast<float2*>(&out[(size_t)(r + 8) * NDIM + col]) = o1;
        }
    }
}

extern "C" void kernel_launch(void* const* d_in, const int* in_sizes, int n_in,
                              void* d_out, int out_size)
{
    const float* x  = (n_in > 0) ? (const float*)d_in[0] : nullptr;
    const float* Ww = (n_in > 1) ? (const float*)d_in[1] : nullptr;
    const float* Wb = (n_in > 2) ? (const float*)d_in[2] : nullptr;
    for (int i = 0; i < n_in; i++) {
        if (in_sizes[i] == X_ELEMS)       x  = (const float*)d_in[i];
        else if (in_sizes[i] == WW_ELEMS) Ww = (const float*)d_in[i];
        else if (in_sizes[i] == WB_ELEMS) Wb = (const float*)d_in[i];
    }

    wsplit_kernel<<<256, 256>>>(Ww);

    static bool attr_set = false;
    if (!attr_set) {
        cudaFuncSetAttribute(fcgat_mma,
                             cudaFuncAttributeMaxDynamicSharedMemorySize,
                             SMEM_TOTAL);
        attr_set = true;
    }
    dim3 grid(NDIM / BN, M_TOT / BM);   // (2, 256)
    fcgat_mma<<<grid, 256, SMEM_TOTAL>>>(x, Wb, (float*)d_out);
}